// round 11
// baseline (speedup 1.0000x reference)
#include <cuda_runtime.h>
#include <cuda_bf16.h>
#include <cstdint>

// PairExcludeMask: out[f,i,n] = type_mask[ atype[f,i]*9 + tj ]
//   tj = (nlist[f,i,n] == -1) ? 8 : atype[f, nlist[f,i,n]]
//
// pack_kernel (128x512, fully parallel):
//   - nibble table: 8 atom types per u32 word, 16KB/frame (+virtual atom)
//   - rowinfo[f][i] = (flag<<16) | rw : rw bit tj = (type_mask[ti*9+tj]!=0),
//     flag: 1=row all-pass, 0=row all-fail, 2=mixed
// mask_kernel: TMA-bulk the nibble table to smem; while in flight, load
// rowinfo + predicated nlist, and store all fast-path rows (no table needed).
// After the mbarrier: slow path = LDS.32 nibble word -> (rw>>tj)&1.

static constexpr int NF     = 4;
static constexpr int NLOC   = 16384;
static constexpr int NNEI   = 128;
static constexpr int NALL   = 32768;
static constexpr int NTYPES = 8;
static constexpr int TM1    = NTYPES + 1;          // 9
static constexpr uint32_t FULL = (1u << TM1) - 1;  // 0x1FF
static constexpr uint32_t ONEF = 0x3F800000u;      // 1.0f bits

static constexpr int WORDS   = NALL / 8;           // 4096 nibble words / frame
static constexpr int WORDS_P = WORDS + 4;          // + virtual atom + pad
static constexpr int TBL_BYTES = WORDS_P * 4;      // 16400

__device__ __align__(16) uint32_t g_nib[NF][WORDS_P];
__device__ __align__(16) uint32_t g_rowinfo[NF][NLOC];   // (flag<<16) | rw

// ---------------- kernel 1: pack nibbles + rowinfo (1 row/thread) ----------------
static constexpr int PK_THREADS = 512;
static constexpr int PK_BLOCKS  = NF * NLOC / PK_THREADS;   // 128

__global__ __launch_bounds__(PK_THREADS)
void pack_kernel(const int* __restrict__ atype, const float* __restrict__ tmask)
{
    __shared__ uint32_t s_rw[16];
    if (threadIdx.x < TM1) {
        uint32_t w = 0;
        #pragma unroll
        for (int tj = 0; tj < TM1; ++tj)
            w |= (tmask[threadIdx.x * TM1 + tj] != 0.0f ? 1u : 0u) << tj;
        s_rw[threadIdx.x] = w;
    }
    __syncthreads();

    const int idx = blockIdx.x * PK_THREADS + threadIdx.x;  // 0 .. 65535

    // --- rowinfo: one row per thread (coalesced) ---
    {
        const int f  = idx >> 14;                  // / NLOC
        const int lr = idx & (NLOC - 1);
        const uint32_t rw = s_rw[__ldg(atype + f * NALL + lr)];
        const uint32_t flag = (rw == FULL) ? 1u : ((rw == 0u) ? 0u : 2u);
        g_rowinfo[f][lr] = (flag << 16) | rw;
    }

    // --- nibble table: first 16K threads, one word each ---
    if (idx < NF * WORDS) {
        const int f  = idx >> 12;                  // / WORDS
        const int wi = idx & (WORDS - 1);
        const int4* __restrict__ at4 = (const int4*)(atype + f * NALL);
        int4 a = at4[wi * 2];
        int4 b = at4[wi * 2 + 1];
        uint32_t p = (uint32_t)a.x        | ((uint32_t)a.y << 4)
                   | ((uint32_t)a.z << 8) | ((uint32_t)a.w << 12)
                   | ((uint32_t)b.x << 16)| ((uint32_t)b.y << 20)
                   | ((uint32_t)b.z << 24)| ((uint32_t)b.w << 28);
        g_nib[f][wi] = p;
        if (wi == 0) {                             // virtual atom j == NALL
            g_nib[f][WORDS]     = (uint32_t)NTYPES;
            g_nib[f][WORDS + 1] = 0;
            g_nib[f][WORDS + 2] = 0;
            g_nib[f][WORDS + 3] = 0;
        }
    }
}

// ---------------- kernel 2: stream the mask ----------------
static constexpr int THREADS_B = 512;
static constexpr int BPF       = 256;                      // blocks per frame
static constexpr int ROWS_PB   = NLOC / BPF;               // 64 rows / block
static constexpr int ROW_VEC   = NNEI / 4;                 // 32 vec4 per row
static constexpr int VEC_PB    = ROWS_PB * ROW_VEC;        // 2048
static constexpr int ITERS     = VEC_PB / THREADS_B;       // 4
static constexpr int BLOCKS_B  = NF * BPF;                 // 1024

static constexpr int SMEM_DYN  = TBL_BYTES;                // 16.4 KB

__global__ __launch_bounds__(THREADS_B)
void mask_kernel(const int4* __restrict__ nlist4,
                 uint4* __restrict__ out4)
{
    extern __shared__ __align__(16) uint32_t s_nib[];   // [WORDS_P]
    __shared__ __align__(8) unsigned long long s_mbar;

    const int tid  = threadIdx.x;
    const int f    = blockIdx.x >> 8;              // / BPF
    const int row0 = (blockIdx.x & (BPF - 1)) * ROWS_PB;

    uint32_t mbar_addr;
    asm("{ .reg .u64 t; cvta.to.shared.u64 t, %1; cvt.u32.u64 %0, t; }"
        : "=r"(mbar_addr) : "l"(&s_mbar));
    uint32_t dst_addr;
    asm("{ .reg .u64 t; cvta.to.shared.u64 t, %1; cvt.u32.u64 %0, t; }"
        : "=r"(dst_addr) : "l"(s_nib));

    if (tid == 0)
        asm volatile("mbarrier.init.shared.b64 [%0], 1;" :: "r"(mbar_addr) : "memory");
    __syncthreads();                               // mbarrier visible

    if (tid == 0) {
        asm volatile("mbarrier.arrive.expect_tx.shared.b64 _, [%0], %1;"
                     :: "r"(mbar_addr), "r"((uint32_t)TBL_BYTES) : "memory");
        asm volatile("cp.async.bulk.shared::cluster.global.mbarrier::complete_tx::bytes "
                     "[%0], [%1], %2, [%3];"
                     :: "r"(dst_addr), "l"(g_nib[f]),
                        "r"((uint32_t)TBL_BYTES), "r"(mbar_addr) : "memory");
    }

    const size_t base = ((size_t)f * NLOC + row0) * ROW_VEC;
    const int4*  __restrict__ nl = nlist4 + base;
    uint4*       __restrict__ ob = out4  + base;

    // ---- overlapped with the TMA copy: rowinfo LDGs (lane-uniform) ----
    uint32_t info[ITERS];
    #pragma unroll
    for (int k = 0; k < ITERS; ++k)
        info[k] = __ldg(&g_rowinfo[f][row0 + ((tid + k * THREADS_B) >> 5)]);

    // ---- still overlapped: predicated nlist loads (MLP=4) ----
    int4 nj[ITERS];
    #pragma unroll
    for (int k = 0; k < ITERS; ++k)
        if ((info[k] >> 16) == 2u)
            nj[k] = nl[tid + k * THREADS_B];

    // ---- still overlapped: fast-path stores (no table dependency) ----
    #pragma unroll
    for (int k = 0; k < ITERS; ++k) {
        const uint32_t flag = info[k] >> 16;
        if (flag != 2u) {
            const uint32_t b = (flag == 1u) ? ONEF : 0u;
            ob[tid + k * THREADS_B] = make_uint4(b, b, b, b);
        }
    }

    // ---- wait for the nibble table ----
    {
        uint32_t done;
        asm volatile(
            "{\n\t.reg .pred p;\n\t"
            "mbarrier.try_wait.parity.acquire.cta.shared::cta.b64 p, [%1], 0;\n\t"
            "selp.b32 %0, 1, 0, p;\n\t}"
            : "=r"(done) : "r"(mbar_addr) : "memory");
        while (!done) {
            asm volatile(
                "{\n\t.reg .pred p;\n\t"
                "mbarrier.try_wait.parity.acquire.cta.shared::cta.b64 p, [%1], 0, 0x989680;\n\t"
                "selp.b32 %0, 1, 0, p;\n\t}"
                : "=r"(done) : "r"(mbar_addr) : "memory");
        }
    }

    // ---- slow path: gather + store ----
    #pragma unroll
    for (int k = 0; k < ITERS; ++k) {
        if ((info[k] >> 16) != 2u) continue;
        const int v = tid + k * THREADS_B;
        const uint32_t rw = info[k] & 0xFFFFu;     // 9-bit row word (warp-uniform)

        uint32_t j0 = min((uint32_t)nj[k].x, (uint32_t)NALL);
        uint32_t j1 = min((uint32_t)nj[k].y, (uint32_t)NALL);
        uint32_t j2 = min((uint32_t)nj[k].z, (uint32_t)NALL);
        uint32_t j3 = min((uint32_t)nj[k].w, (uint32_t)NALL);

        uint32_t w0 = s_nib[j0 >> 3];
        uint32_t w1 = s_nib[j1 >> 3];
        uint32_t w2 = s_nib[j2 >> 3];
        uint32_t w3 = s_nib[j3 >> 3];

        uint32_t t0 = (w0 >> ((j0 & 7u) << 2)) & 15u;
        uint32_t t1 = (w1 >> ((j1 & 7u) << 2)) & 15u;
        uint32_t t2 = (w2 >> ((j2 & 7u) << 2)) & 15u;
        uint32_t t3 = (w3 >> ((j3 & 7u) << 2)) & 15u;

        uint4 r;
        r.x = ((rw >> t0) & 1u) ? ONEF : 0u;
        r.y = ((rw >> t1) & 1u) ? ONEF : 0u;
        r.z = ((rw >> t2) & 1u) ? ONEF : 0u;
        r.w = ((rw >> t3) & 1u) ? ONEF : 0u;

        ob[v] = r;
    }
}

extern "C" void kernel_launch(void* const* d_in, const int* in_sizes, int n_in,
                              void* d_out, int out_size)
{
    const int4*  nlist4 = (const int4*) d_in[0];
    const int*   atype  = (const int*)  d_in[1];
    const float* tmask  = (const float*)d_in[2];
    // d_in[3] = ntypes scalar (8, baked into constants)

    uint4* out4 = (uint4*)d_out;

    static bool configured = false;
    if (!configured) {
        cudaFuncSetAttribute(mask_kernel,
                             cudaFuncAttributeMaxDynamicSharedMemorySize,
                             SMEM_DYN);
        cudaFuncSetAttribute(mask_kernel,
                             cudaFuncAttributePreferredSharedMemoryCarveout,
                             100);
        configured = true;
    }

    pack_kernel<<<PK_BLOCKS, PK_THREADS>>>(atype, tmask);
    mask_kernel<<<BLOCKS_B, THREADS_B, SMEM_DYN>>>(nlist4, out4);
}